// round 1
// baseline (speedup 1.0000x reference)
#include <cuda_runtime.h>

#define Hh 126
#define Ww 126
#define WP 128
#define NPIX (Hh*Ww)        // 15876
#define PLANE (Hh*WP)       // 16128
#define NLAYER 6

// ping-pong activation buffers + involution weight buffer
__device__ float g_x[64*PLANE];     // ~4.1 MB
__device__ float g_y[64*PLANE];     // ~4.1 MB
__device__ float g_w[196*PLANE];    // ~12.6 MB

// ---------------------------------------------------------------------------
// conv_in: (1,3,128,128) -> (1,64,126,126), 3x3 valid conv
// ---------------------------------------------------------------------------
__global__ __launch_bounds__(256) void k_conv_in(const float* __restrict__ in,
                                                 const float* __restrict__ wt,
                                                 const float* __restrict__ bias,
                                                 float* __restrict__ out)
{
    int t = blockIdx.x * 256 + threadIdx.x;      // over 126*128 padded plane
    int c = blockIdx.y;
    int y = t >> 7, x = t & 127;
    if (y >= Hh || x >= Ww) return;
    float acc = bias[c];
    const float* wc = wt + c * 27;
    #pragma unroll
    for (int i = 0; i < 3; i++)
        #pragma unroll
        for (int r = 0; r < 3; r++)
            #pragma unroll
            for (int s = 0; s < 3; s++)
                acc += wc[(i*3+r)*3+s] * in[(i*128 + (y+r))*128 + (x+s)];
    out[c*PLANE + y*WP + x] = acc;
}

// ---------------------------------------------------------------------------
// kgen: per 64-pixel chunk: t = relu(bn(Wr@x + br)); w = Ws@t + bs -> g_w
// ---------------------------------------------------------------------------
__global__ __launch_bounds__(256) void k_kgen(const float* __restrict__ src,
    const float* __restrict__ wr, const float* __restrict__ br,
    const float* __restrict__ gmm, const float* __restrict__ bet,
    const float* __restrict__ mu, const float* __restrict__ var,
    const float* __restrict__ ws, const float* __restrict__ bs)
{
    __shared__ float xs[64][64];     // [ic][p]
    __shared__ float ts[16][64];     // [c][p]
    __shared__ float wrs[64][16];    // transposed reduce weights [ic][c]
    __shared__ float wss[16][200];   // transposed span weights [c][j] (pad 200)
    __shared__ float bss[196];
    __shared__ float sc[16], sh[16];

    int tid = threadIdx.x;
    int pix0 = blockIdx.x * 64;

    for (int idx = tid; idx < 1024; idx += 256) wrs[idx & 63][idx >> 6] = wr[idx];
    for (int idx = tid; idx < 3136; idx += 256) wss[idx & 15][idx >> 4] = ws[idx];
    if (tid < 196) bss[tid] = bs[tid];
    if (tid < 16) {
        float s = gmm[tid] * rsqrtf(var[tid] + 1e-5f);
        sc[tid] = s;
        sh[tid] = (br[tid] - mu[tid]) * s + bet[tid];
    }
    for (int idx = tid; idx < 4096; idx += 256) {
        int ic = idx >> 6, p = idx & 63;
        int pix = pix0 + p;
        float v = 0.f;
        if (pix < NPIX) {
            int y = pix / 126, x = pix - y * 126;
            v = src[ic*PLANE + y*WP + x];
        }
        xs[ic][p] = v;
    }
    __syncthreads();

    // stage 2: t[16][64]  (128 active threads: 32 pixel-pairs x 4 channel-quads)
    if (tid < 128) {
        int p0 = (tid & 31) * 2;
        int c0 = (tid >> 5) * 4;
        float a00=0,a01=0,a10=0,a11=0,a20=0,a21=0,a30=0,a31=0;
        #pragma unroll 8
        for (int ic = 0; ic < 64; ic++) {
            float2 xv = *(const float2*)&xs[ic][p0];
            float4 wv = *(const float4*)&wrs[ic][c0];
            a00 += wv.x*xv.x; a01 += wv.x*xv.y;
            a10 += wv.y*xv.x; a11 += wv.y*xv.y;
            a20 += wv.z*xv.x; a21 += wv.z*xv.y;
            a30 += wv.w*xv.x; a31 += wv.w*xv.y;
        }
        float s0=sc[c0],   h0=sh[c0];
        float s1=sc[c0+1], h1=sh[c0+1];
        float s2=sc[c0+2], h2=sh[c0+2];
        float s3=sc[c0+3], h3=sh[c0+3];
        ts[c0  ][p0] = fmaxf(a00*s0+h0, 0.f); ts[c0  ][p0+1] = fmaxf(a01*s0+h0, 0.f);
        ts[c0+1][p0] = fmaxf(a10*s1+h1, 0.f); ts[c0+1][p0+1] = fmaxf(a11*s1+h1, 0.f);
        ts[c0+2][p0] = fmaxf(a20*s2+h2, 0.f); ts[c0+2][p0+1] = fmaxf(a21*s2+h2, 0.f);
        ts[c0+3][p0] = fmaxf(a30*s3+h3, 0.f); ts[c0+3][p0+1] = fmaxf(a31*s3+h3, 0.f);
    }
    __syncthreads();

    // stage 3: w[196][64] = Ws @ t  (all 256 threads: 32 pixel-pairs x 8 j-quad groups)
    int p0 = (tid & 31) * 2;
    int jq = tid >> 5;
    int pixA = pix0 + p0, pixB = pixA + 1;
    bool vA = pixA < NPIX, vB = pixB < NPIX;
    int addrA = 0, addrB = 0;
    if (vA) { int y = pixA / 126; addrA = y*WP + (pixA - y*126); }
    if (vB) { int y = pixB / 126; addrB = y*WP + (pixB - y*126); }

    #pragma unroll 1
    for (int jb = 4*jq; jb < 196; jb += 32) {
        float a0A = bss[jb],   a0B = a0A;
        float a1A = bss[jb+1], a1B = a1A;
        float a2A = bss[jb+2], a2B = a2A;
        float a3A = bss[jb+3], a3B = a3A;
        #pragma unroll
        for (int c = 0; c < 16; c++) {
            float2 tv = *(const float2*)&ts[c][p0];
            float4 wv = *(const float4*)&wss[c][jb];
            a0A += wv.x*tv.x; a0B += wv.x*tv.y;
            a1A += wv.y*tv.x; a1B += wv.y*tv.y;
            a2A += wv.z*tv.x; a2B += wv.z*tv.y;
            a3A += wv.w*tv.x; a3B += wv.w*tv.y;
        }
        if (vA) {
            g_w[(jb  )*PLANE + addrA] = a0A;
            g_w[(jb+1)*PLANE + addrA] = a1A;
            g_w[(jb+2)*PLANE + addrA] = a2A;
            g_w[(jb+3)*PLANE + addrA] = a3A;
        }
        if (vB) {
            g_w[(jb  )*PLANE + addrB] = a0B;
            g_w[(jb+1)*PLANE + addrB] = a1B;
            g_w[(jb+2)*PLANE + addrB] = a2B;
            g_w[(jb+3)*PLANE + addrB] = a3B;
        }
    }
}

// ---------------------------------------------------------------------------
// agg: involution aggregation + relu.
// grid (2, 16, 4): 64x8 pixel tile per block for one group. block (16,8).
// dynamic smem: xs[16][14][72] + wsh[49][512]
// ---------------------------------------------------------------------------
#define AGG_XS (16*14*72)
#define AGG_WS (49*512)
#define AGG_SMEM ((AGG_XS + AGG_WS) * 4)

__global__ __launch_bounds__(128) void k_agg(const float* __restrict__ src,
                                             float* __restrict__ dst)
{
    extern __shared__ float sm[];
    float* xs  = sm;
    float* wsh = sm + AGG_XS;
    int g = blockIdx.z;
    int x0 = blockIdx.x * 64, y0 = blockIdx.y * 8;
    int tid = threadIdx.y * 16 + threadIdx.x;

    for (int idx = tid; idx < 16*14*70; idx += 128) {
        int c = idx / 980; int rem = idx - c*980;
        int r = rem / 70;  int col = rem - r*70;
        int gy = y0 + r - 3, gx = x0 + col - 3;
        float v = 0.f;
        if ((unsigned)gy < 126u && (unsigned)gx < 126u)
            v = src[(g*16 + c)*PLANE + gy*WP + gx];
        xs[(c*14 + r)*72 + col] = v;
    }
    for (int idx = tid; idx < AGG_WS; idx += 128) {
        int k = idx >> 9; int p = idx & 511;
        int gy = y0 + (p >> 6), gx = x0 + (p & 63);
        float v = 0.f;
        if (gy < 126 && gx < 126)
            v = g_w[(g*49 + k)*PLANE + gy*WP + gx];
        wsh[idx] = v;
    }
    __syncthreads();

    int tx = threadIdx.x, ty = threadIdx.y;
    int xb = tx * 4;
    int gy = y0 + ty;

    #pragma unroll 1
    for (int cb = 0; cb < 4; cb++) {
        float acc[4][4] = {};
        #pragma unroll 1
        for (int kh = 0; kh < 7; kh++) {
            float xr[4][12];
            #pragma unroll
            for (int cc = 0; cc < 4; cc++) {
                const float* base = &xs[((cb*4 + cc)*14 + ty + kh)*72 + xb];
                float4 v0 = *(const float4*)(base);
                float4 v1 = *(const float4*)(base + 4);
                float4 v2 = *(const float4*)(base + 8);
                xr[cc][0]=v0.x; xr[cc][1]=v0.y; xr[cc][2]=v0.z; xr[cc][3]=v0.w;
                xr[cc][4]=v1.x; xr[cc][5]=v1.y; xr[cc][6]=v1.z; xr[cc][7]=v1.w;
                xr[cc][8]=v2.x; xr[cc][9]=v2.y; xr[cc][10]=v2.z; xr[cc][11]=v2.w;
            }
            #pragma unroll
            for (int kw = 0; kw < 7; kw++) {
                float4 wv = *(const float4*)&wsh[(kh*7 + kw)*512 + ty*64 + xb];
                #pragma unroll
                for (int cc = 0; cc < 4; cc++) {
                    acc[cc][0] += wv.x * xr[cc][kw];
                    acc[cc][1] += wv.y * xr[cc][kw+1];
                    acc[cc][2] += wv.z * xr[cc][kw+2];
                    acc[cc][3] += wv.w * xr[cc][kw+3];
                }
            }
        }
        if (gy < 126) {
            #pragma unroll
            for (int cc = 0; cc < 4; cc++) {
                int ch = g*16 + cb*4 + cc;
                float* o = &dst[ch*PLANE + gy*WP + x0 + xb];
                #pragma unroll
                for (int q = 0; q < 4; q++)
                    if (x0 + xb + q < 126) o[q] = fmaxf(acc[cc][q], 0.f);
            }
        }
    }
}

// ---------------------------------------------------------------------------
// conv_out: (64,126,126) -> (128,124,124), 3x3 valid conv.
// grid (124 rows, 4 oc-groups), block 256 = 8 colgroups x 32 oc.
// ---------------------------------------------------------------------------
#define CO_XS (16*3*132)
#define CO_WS (32*16*12)
#define CO_SMEM ((CO_XS + CO_WS) * 4)

__global__ __launch_bounds__(256) void k_conv_out(const float* __restrict__ src,
    const float* __restrict__ wt, const float* __restrict__ bias,
    float* __restrict__ out)
{
    extern __shared__ float sm[];
    float* xs  = sm;            // [16][3][132]
    float* wsh = sm + CO_XS;    // [32][16][12]
    int y = blockIdx.x;         // output row 0..123
    int ocg = blockIdx.y;       // 0..3
    int tid = threadIdx.x;
    int cg = tid & 7, oc_l = tid >> 3;
    int oc = ocg*32 + oc_l;
    float acc[16] = {};

    for (int icc = 0; icc < 4; icc++) {
        __syncthreads();
        for (int idx = tid; idx < CO_XS; idx += 256) {
            int ic = idx / 396; int rem = idx - ic*396;
            int r = rem / 132;  int col = rem - r*132;
            float v = 0.f;
            if (col < 126) v = src[(icc*16 + ic)*PLANE + (y + r)*WP + col];
            xs[idx] = v;
        }
        for (int idx = tid; idx < CO_WS; idx += 256) {
            int o = idx / 192; int rem = idx - o*192;
            int ic = rem / 12; int k = rem - ic*12;
            wsh[idx] = (k < 9) ? wt[(ocg*32 + o)*576 + (icc*16 + ic)*9 + k] : 0.f;
        }
        __syncthreads();

        #pragma unroll 2
        for (int ic = 0; ic < 16; ic++) {
            float wreg[9];
            {
                const float* wb = &wsh[(oc_l*16 + ic)*12];
                float4 w0 = *(const float4*)wb;
                float4 w1 = *(const float4*)(wb + 4);
                wreg[0]=w0.x; wreg[1]=w0.y; wreg[2]=w0.z; wreg[3]=w0.w;
                wreg[4]=w1.x; wreg[5]=w1.y; wreg[6]=w1.z; wreg[7]=w1.w;
                wreg[8]=wb[8];
            }
            #pragma unroll
            for (int kh = 0; kh < 3; kh++) {
                float xr[18];
                const float* xb = &xs[(ic*3 + kh)*132 + cg*16];
                float4 a0 = *(const float4*)(xb);
                float4 a1 = *(const float4*)(xb + 4);
                float4 a2 = *(const float4*)(xb + 8);
                float4 a3 = *(const float4*)(xb + 12);
                float2 a4 = *(const float2*)(xb + 16);
                xr[0]=a0.x; xr[1]=a0.y; xr[2]=a0.z; xr[3]=a0.w;
                xr[4]=a1.x; xr[5]=a1.y; xr[6]=a1.z; xr[7]=a1.w;
                xr[8]=a2.x; xr[9]=a2.y; xr[10]=a2.z; xr[11]=a2.w;
                xr[12]=a3.x; xr[13]=a3.y; xr[14]=a3.z; xr[15]=a3.w;
                xr[16]=a4.x; xr[17]=a4.y;
                #pragma unroll
                for (int kw = 0; kw < 3; kw++) {
                    float w = wreg[kh*3 + kw];
                    #pragma unroll
                    for (int p = 0; p < 16; p++)
                        acc[p] += w * xr[p + kw];
                }
            }
        }
    }

    float bv = bias[oc];
    int xbase = cg * 16;
    float* o = &out[(oc*124 + y)*124 + xbase];
    #pragma unroll
    for (int p = 0; p < 16; p++)
        if (xbase + p < 124) o[p] = acc[p] + bv;
}

// ---------------------------------------------------------------------------
extern "C" void kernel_launch(void* const* d_in, const int* in_sizes, int n_in,
                              void* d_out, int out_size)
{
    const float* input = (const float*)d_in[0];
    const float* ciw   = (const float*)d_in[1];
    const float* cib   = (const float*)d_in[2];
    const float* wr    = (const float*)d_in[3];
    const float* brr   = (const float*)d_in[4];
    const float* gmm   = (const float*)d_in[5];
    const float* bet   = (const float*)d_in[6];
    const float* mu    = (const float*)d_in[7];
    const float* var   = (const float*)d_in[8];
    const float* ws    = (const float*)d_in[9];
    const float* bs    = (const float*)d_in[10];
    const float* cow   = (const float*)d_in[11];
    const float* cob   = (const float*)d_in[12];

    float *px, *py;
    cudaGetSymbolAddress((void**)&px, g_x);
    cudaGetSymbolAddress((void**)&py, g_y);
    cudaFuncSetAttribute(k_agg, cudaFuncAttributeMaxDynamicSharedMemorySize, AGG_SMEM);
    cudaFuncSetAttribute(k_conv_out, cudaFuncAttributeMaxDynamicSharedMemorySize, CO_SMEM);

    k_conv_in<<<dim3(63, 64), 256>>>(input, ciw, cib, px);

    float* cur = px;
    float* nxt = py;
    for (int l = 0; l < NLAYER; l++) {
        k_kgen<<<249, 256>>>(cur, wr + l*1024, brr + l*16, gmm + l*16, bet + l*16,
                             mu + l*16, var + l*16, ws + l*3136, bs + l*196);
        k_agg<<<dim3(2, 16, 4), dim3(16, 8), AGG_SMEM>>>(cur, nxt);
        float* t = cur; cur = nxt; nxt = t;
    }
    k_conv_out<<<dim3(124, 4), 256, CO_SMEM>>>(cur, cow, cob, (float*)d_out);
}

// round 2
// speedup vs baseline: 1.1769x; 1.1769x over previous
#include <cuda_runtime.h>

#define Hh 126
#define Ww 126
#define WP 128
#define NPIX (Hh*Ww)        // 15876
#define PLANE (Hh*WP)       // 16128
#define NLAYER 6

// ping-pong activation buffers + involution weight buffer
__device__ float g_x[64*PLANE];     // ~4.1 MB
__device__ float g_y[64*PLANE];     // ~4.1 MB
__device__ float g_w[196*PLANE];    // ~12.6 MB

// ---------------------------------------------------------------------------
// conv_in: (1,3,128,128) -> (1,64,126,126), 3x3 valid conv
// ---------------------------------------------------------------------------
__global__ __launch_bounds__(256) void k_conv_in(const float* __restrict__ in,
                                                 const float* __restrict__ wt,
                                                 const float* __restrict__ bias,
                                                 float* __restrict__ out)
{
    int t = blockIdx.x * 256 + threadIdx.x;      // over 126*128 padded plane
    int c = blockIdx.y;
    int y = t >> 7, x = t & 127;
    if (y >= Hh || x >= Ww) return;
    float acc = bias[c];
    const float* wc = wt + c * 27;
    #pragma unroll
    for (int i = 0; i < 3; i++)
        #pragma unroll
        for (int r = 0; r < 3; r++)
            #pragma unroll
            for (int s = 0; s < 3; s++)
                acc += wc[(i*3+r)*3+s] * in[(i*128 + (y+r))*128 + (x+s)];
    out[c*PLANE + y*WP + x] = acc;
}

// ---------------------------------------------------------------------------
// kgen: thread-per-pixel. t[16] in registers, weights broadcast from shared.
// block = 64 threads = 64 pixels; grid 249.
// ---------------------------------------------------------------------------
__global__ __launch_bounds__(64) void k_kgen(const float* __restrict__ src,
    const float* __restrict__ wr, const float* __restrict__ br,
    const float* __restrict__ gmm, const float* __restrict__ bet,
    const float* __restrict__ mu, const float* __restrict__ var,
    const float* __restrict__ ws, const float* __restrict__ bs)
{
    __shared__ alignas(16) float xs[64*64];     // [ic][p]
    __shared__ alignas(16) float wrs[64*16];    // transposed reduce weights [ic][c]
    __shared__ alignas(16) float wst[16*200];   // transposed span weights [c][j]
    __shared__ alignas(16) float bss[196];
    __shared__ float scs[16], shs[16];

    int tid = threadIdx.x;
    int pix0 = blockIdx.x * 64;

    for (int i = tid; i < 1024; i += 64) wrs[(i & 63)*16 + (i >> 6)] = wr[i];
    for (int i = tid; i < 3136; i += 64) wst[(i & 15)*200 + (i >> 4)] = ws[i];
    for (int i = tid; i < 196; i += 64) bss[i] = bs[i];
    if (tid < 16) {
        float s = gmm[tid] * rsqrtf(var[tid] + 1e-5f);
        scs[tid] = s;
        shs[tid] = (br[tid] - mu[tid]) * s + bet[tid];
    }

    int pix = pix0 + tid;
    bool valid = pix < NPIX;
    int yy = pix < NPIX ? pix / 126 : 0;
    int xx = pix < NPIX ? pix - yy * 126 : 0;
    int addr = yy * WP + xx;

    #pragma unroll 4
    for (int ic = 0; ic < 64; ic++)
        xs[ic*64 + tid] = valid ? src[ic*PLANE + addr] : 0.f;
    __syncthreads();

    // stage 2: t[16] per thread
    float t[16];
    #pragma unroll
    for (int c = 0; c < 16; c++) t[c] = 0.f;
    #pragma unroll 4
    for (int ic = 0; ic < 64; ic++) {
        float xv = xs[ic*64 + tid];
        #pragma unroll
        for (int c4 = 0; c4 < 4; c4++) {
            float4 wv = *(const float4*)&wrs[ic*16 + c4*4];
            t[c4*4+0] += wv.x * xv;
            t[c4*4+1] += wv.y * xv;
            t[c4*4+2] += wv.z * xv;
            t[c4*4+3] += wv.w * xv;
        }
    }
    #pragma unroll
    for (int c = 0; c < 16; c++)
        t[c] = fmaxf(t[c] * scs[c] + shs[c], 0.f);

    // stage 3: w[196] = Ws @ t, streamed to g_w
    #pragma unroll 1
    for (int j4 = 0; j4 < 49; j4++) {
        float4 bv = *(const float4*)&bss[j4*4];
        float a0 = bv.x, a1 = bv.y, a2 = bv.z, a3 = bv.w;
        #pragma unroll
        for (int c = 0; c < 16; c++) {
            float4 wv = *(const float4*)&wst[c*200 + j4*4];
            a0 += wv.x * t[c];
            a1 += wv.y * t[c];
            a2 += wv.z * t[c];
            a3 += wv.w * t[c];
        }
        if (valid) {
            float* o = g_w + (j4*4)*PLANE + addr;
            o[0]       = a0;
            o[PLANE]   = a1;
            o[2*PLANE] = a2;
            o[3*PLANE] = a3;
        }
    }
}

// ---------------------------------------------------------------------------
// agg: involution aggregation + relu.
// Tile 32x16 px, 8 channels (half a group) per block. 128 threads,
// 4 px x 8 ch per thread. x-halo in swizzled smem (16B = 4 channels),
// per-pixel kernels read directly from gmem as float4.
// grid (4, 8, 8): x-tiles, y-tiles, group*2+half.
// ---------------------------------------------------------------------------
#define AGG_ROWS 22
#define AGG_PCH  40                       // chunks per (row, c4): 38 used, pad->40 (128B-aligned bases)
#define AGG_CHUNKS (AGG_ROWS*2*AGG_PCH)   // 1760 chunks = 28160 B

__global__ __launch_bounds__(128) void k_agg(const float* __restrict__ src,
                                             float* __restrict__ dst)
{
    __shared__ alignas(16) float xs[AGG_CHUNKS*4];

    int g    = blockIdx.z >> 1;
    int half = blockIdx.z & 1;
    int x0 = blockIdx.x * 32, y0 = blockIdx.y * 16;
    int tid = threadIdx.x;

    // loader: 8 channels x 22 rows x 38 positions, zero-padded halo
    for (int i = tid; i < 8*22*38; i += 128) {
        int c = i / 836; int rem = i - c*836;
        int r = rem / 38; int p = rem - r*38;
        int gy = y0 + r - 3, gx = x0 + p - 3;
        float v = 0.f;
        if ((unsigned)gy < 126u && (unsigned)gx < 126u)
            v = src[(g*16 + half*8 + c)*PLANE + gy*WP + gx];
        int chunk = (r*2 + (c >> 2))*AGG_PCH + p;
        int byte = chunk * 16;
        int sw = byte ^ ((byte >> 3) & 0x70);
        *(float*)((char*)xs + sw + (c & 3)*4) = v;
    }
    __syncthreads();

    int ty = tid >> 3;            // 0..15
    int xb = (tid & 7) * 4;       // 0,4,...,28
    int gy = y0 + ty;
    if (gy >= 126) return;
    int gx0 = x0 + xb;

    const float* wbase = g_w + (g*49)*PLANE + gy*WP + gx0;

    float acc[8][4];
    #pragma unroll
    for (int cc = 0; cc < 8; cc++)
        #pragma unroll
        for (int q = 0; q < 4; q++) acc[cc][q] = 0.f;

    #pragma unroll 1
    for (int kh = 0; kh < 7; kh++) {
        float4 wv[7];
        #pragma unroll
        for (int kw = 0; kw < 7; kw++)
            wv[kw] = *(const float4*)(wbase + (kh*7 + kw)*PLANE);

        #pragma unroll
        for (int cg = 0; cg < 2; cg++) {
            int rowbase = ((ty + kh)*2 + cg)*AGG_PCH;
            float4 xq[10];
            #pragma unroll
            for (int j = 0; j < 10; j++) {
                int byte = (rowbase + xb + j) * 16;
                int sw = byte ^ ((byte >> 3) & 0x70);
                xq[j] = *(const float4*)((const char*)xs + sw);
            }
            #pragma unroll
            for (int kw = 0; kw < 7; kw++) {
                #pragma unroll
                for (int q = 0; q < 4; q++) {
                    float w = (q == 0) ? wv[kw].x : (q == 1) ? wv[kw].y
                            : (q == 2) ? wv[kw].z : wv[kw].w;
                    float4 xv = xq[q + kw];
                    acc[cg*4+0][q] += w * xv.x;
                    acc[cg*4+1][q] += w * xv.y;
                    acc[cg*4+2][q] += w * xv.z;
                    acc[cg*4+3][q] += w * xv.w;
                }
            }
        }
    }

    #pragma unroll
    for (int cc = 0; cc < 8; cc++) {
        int ch = g*16 + half*8 + cc;
        float* o = dst + ch*PLANE + gy*WP + gx0;
        #pragma unroll
        for (int q = 0; q < 4; q++)
            if (gx0 + q < 126) o[q] = fmaxf(acc[cc][q], 0.f);
    }
}

// ---------------------------------------------------------------------------
// conv_out: (64,126,126) -> (128,124,124), 3x3 valid conv.
// grid (124 rows, 4 oc-groups), block 256 = 8 colgroups x 32 oc.
// ---------------------------------------------------------------------------
#define CO_XS (16*3*132)
#define CO_WS (32*16*12)
#define CO_SMEM ((CO_XS + CO_WS) * 4)

__global__ __launch_bounds__(256) void k_conv_out(const float* __restrict__ src,
    const float* __restrict__ wt, const float* __restrict__ bias,
    float* __restrict__ out)
{
    extern __shared__ float sm[];
    float* xs  = sm;            // [16][3][132]
    float* wsh = sm + CO_XS;    // [32][16][12]
    int y = blockIdx.x;         // output row 0..123
    int ocg = blockIdx.y;       // 0..3
    int tid = threadIdx.x;
    int cg = tid & 7, oc_l = tid >> 3;
    int oc = ocg*32 + oc_l;
    float acc[16] = {};

    for (int icc = 0; icc < 4; icc++) {
        __syncthreads();
        for (int idx = tid; idx < CO_XS; idx += 256) {
            int ic = idx / 396; int rem = idx - ic*396;
            int r = rem / 132;  int col = rem - r*132;
            float v = 0.f;
            if (col < 126) v = src[(icc*16 + ic)*PLANE + (y + r)*WP + col];
            xs[idx] = v;
        }
        for (int idx = tid; idx < CO_WS; idx += 256) {
            int o = idx / 192; int rem = idx - o*192;
            int ic = rem / 12; int k = rem - ic*12;
            wsh[idx] = (k < 9) ? wt[(ocg*32 + o)*576 + (icc*16 + ic)*9 + k] : 0.f;
        }
        __syncthreads();

        #pragma unroll 2
        for (int ic = 0; ic < 16; ic++) {
            float wreg[9];
            {
                const float* wb = &wsh[(oc_l*16 + ic)*12];
                float4 w0 = *(const float4*)wb;
                float4 w1 = *(const float4*)(wb + 4);
                wreg[0]=w0.x; wreg[1]=w0.y; wreg[2]=w0.z; wreg[3]=w0.w;
                wreg[4]=w1.x; wreg[5]=w1.y; wreg[6]=w1.z; wreg[7]=w1.w;
                wreg[8]=wb[8];
            }
            #pragma unroll
            for (int kh = 0; kh < 3; kh++) {
                float xr[18];
                const float* xb = &xs[(ic*3 + kh)*132 + cg*16];
                float4 a0 = *(const float4*)(xb);
                float4 a1 = *(const float4*)(xb + 4);
                float4 a2 = *(const float4*)(xb + 8);
                float4 a3 = *(const float4*)(xb + 12);
                float2 a4 = *(const float2*)(xb + 16);
                xr[0]=a0.x; xr[1]=a0.y; xr[2]=a0.z; xr[3]=a0.w;
                xr[4]=a1.x; xr[5]=a1.y; xr[6]=a1.z; xr[7]=a1.w;
                xr[8]=a2.x; xr[9]=a2.y; xr[10]=a2.z; xr[11]=a2.w;
                xr[12]=a3.x; xr[13]=a3.y; xr[14]=a3.z; xr[15]=a3.w;
                xr[16]=a4.x; xr[17]=a4.y;
                #pragma unroll
                for (int kw = 0; kw < 3; kw++) {
                    float w = wreg[kh*3 + kw];
                    #pragma unroll
                    for (int p = 0; p < 16; p++)
                        acc[p] += w * xr[p + kw];
                }
            }
        }
    }

    float bv = bias[oc];
    int xbase = cg * 16;
    float* o = &out[(oc*124 + y)*124 + xbase];
    #pragma unroll
    for (int p = 0; p < 16; p++)
        if (xbase + p < 124) o[p] = acc[p] + bv;
}

// ---------------------------------------------------------------------------
extern "C" void kernel_launch(void* const* d_in, const int* in_sizes, int n_in,
                              void* d_out, int out_size)
{
    const float* input = (const float*)d_in[0];
    const float* ciw   = (const float*)d_in[1];
    const float* cib   = (const float*)d_in[2];
    const float* wr    = (const float*)d_in[3];
    const float* brr   = (const float*)d_in[4];
    const float* gmm   = (const float*)d_in[5];
    const float* bet   = (const float*)d_in[6];
    const float* mu    = (const float*)d_in[7];
    const float* var   = (const float*)d_in[8];
    const float* ws    = (const float*)d_in[9];
    const float* bs    = (const float*)d_in[10];
    const float* cow   = (const float*)d_in[11];
    const float* cob   = (const float*)d_in[12];

    float *px, *py;
    cudaGetSymbolAddress((void**)&px, g_x);
    cudaGetSymbolAddress((void**)&py, g_y);
    cudaFuncSetAttribute(k_conv_out, cudaFuncAttributeMaxDynamicSharedMemorySize, CO_SMEM);

    k_conv_in<<<dim3(63, 64), 256>>>(input, ciw, cib, px);

    float* cur = px;
    float* nxt = py;
    for (int l = 0; l < NLAYER; l++) {
        k_kgen<<<249, 64>>>(cur, wr + l*1024, brr + l*16, gmm + l*16, bet + l*16,
                            mu + l*16, var + l*16, ws + l*3136, bs + l*196);
        k_agg<<<dim3(4, 8, 8), 128>>>(cur, nxt);
        float* t = cur; cur = nxt; nxt = t;
    }
    k_conv_out<<<dim3(124, 4), 256, CO_SMEM>>>(cur, cow, cob, (float*)d_out);
}

// round 3
// speedup vs baseline: 1.2767x; 1.0848x over previous
#include <cuda_runtime.h>

#define Hh 126
#define Ww 126
#define WP 128
#define NPIX (Hh*Ww)        // 15876
#define PLANE (Hh*WP)       // 16128
#define NLAYER 6

// ping-pong activation buffers + involution weight buffer
__device__ float g_x[64*PLANE];     // ~4.1 MB
__device__ float g_y[64*PLANE];     // ~4.1 MB
__device__ float g_w[196*PLANE];    // ~12.6 MB

// ---------------------------------------------------------------------------
// conv_in: (1,3,128,128) -> (1,64,126,126), 3x3 valid conv
// ---------------------------------------------------------------------------
__global__ __launch_bounds__(256) void k_conv_in(const float* __restrict__ in,
                                                 const float* __restrict__ wt,
                                                 const float* __restrict__ bias,
                                                 float* __restrict__ out)
{
    int t = blockIdx.x * 256 + threadIdx.x;      // over 126*128 padded plane
    int c = blockIdx.y;
    int y = t >> 7, x = t & 127;
    if (y >= Hh || x >= Ww) return;
    float acc = bias[c];
    const float* wc = wt + c * 27;
    #pragma unroll
    for (int i = 0; i < 3; i++)
        #pragma unroll
        for (int r = 0; r < 3; r++)
            #pragma unroll
            for (int s = 0; s < 3; s++)
                acc += wc[(i*3+r)*3+s] * in[(i*128 + (y+r))*128 + (x+s)];
    out[c*PLANE + y*WP + x] = acc;
}

// ---------------------------------------------------------------------------
// kgen v3: 256 threads / 64 pixels.
// Phase A: 4 threads per pixel (one c-quad each) -> ts[16][72] with BN+ReLU.
// Phase B: 4 threads per pixel, j strided by 4 (49 j's each), span weights
//          [j][c] row-major -> warp-uniform float4 broadcasts.
// ---------------------------------------------------------------------------
__global__ __launch_bounds__(256) void k_kgen(const float* __restrict__ src,
    const float* __restrict__ wr, const float* __restrict__ br,
    const float* __restrict__ gmm, const float* __restrict__ bet,
    const float* __restrict__ mu, const float* __restrict__ var,
    const float* __restrict__ ws, const float* __restrict__ bs)
{
    __shared__ alignas(16) float xs[64*64];      // [ic][p]
    __shared__ alignas(16) float wrs[64*16];     // transposed reduce weights [ic][c]
    __shared__ alignas(16) float wsj[196*16];    // span weights [j][c] (native layout)
    __shared__ alignas(16) float bss[196];
    __shared__ alignas(16) float ts[16*72];      // t activations [c][p] (pad 72)
    __shared__ float scs[16], shs[16];

    int tid = threadIdx.x;
    int pix0 = blockIdx.x * 64;
    int p  = tid & 63;
    int q4 = tid >> 6;       // 0..3

    for (int i = tid; i < 1024; i += 256) wrs[(i & 63)*16 + (i >> 6)] = wr[i];
    for (int i = tid; i < 3136; i += 256) wsj[i] = ws[i];
    if (tid < 196) bss[tid] = bs[tid];
    if (tid < 16) {
        float s = gmm[tid] * rsqrtf(var[tid] + 1e-5f);
        scs[tid] = s;
        shs[tid] = (br[tid] - mu[tid]) * s + bet[tid];
    }

    int pix = pix0 + p;
    bool valid = pix < NPIX;
    int yy = valid ? pix / 126 : 0;
    int xx = valid ? pix - yy * 126 : 0;
    int addr = yy * WP + xx;

    // stage x into shared (coalesced; each thread 16 values)
    for (int i = tid; i < 4096; i += 256) {
        int ic = i >> 6, pp = i & 63;
        int px2 = pix0 + pp;
        float v = 0.f;
        if (px2 < NPIX) {
            int y2 = px2 / 126;
            v = src[ic*PLANE + y2*WP + (px2 - y2*126)];
        }
        xs[ic*64 + pp] = v;
    }
    __syncthreads();

    // Phase A: c-quad q4 for pixel p
    {
        int c0 = q4 * 4;
        float a0 = 0.f, a1 = 0.f, a2 = 0.f, a3 = 0.f;
        #pragma unroll 8
        for (int ic = 0; ic < 64; ic++) {
            float xv = xs[ic*64 + p];                       // conflict-free
            float4 wv = *(const float4*)&wrs[ic*16 + c0];   // warp-uniform broadcast
            a0 += wv.x * xv;
            a1 += wv.y * xv;
            a2 += wv.z * xv;
            a3 += wv.w * xv;
        }
        ts[(c0  )*72 + p] = fmaxf(a0 * scs[c0  ] + shs[c0  ], 0.f);
        ts[(c0+1)*72 + p] = fmaxf(a1 * scs[c0+1] + shs[c0+1], 0.f);
        ts[(c0+2)*72 + p] = fmaxf(a2 * scs[c0+2] + shs[c0+2], 0.f);
        ts[(c0+3)*72 + p] = fmaxf(a3 * scs[c0+3] + shs[c0+3], 0.f);
    }
    __syncthreads();

    // Phase B: t[16] in registers; j = jj*4 + q4 (49 outputs per thread)
    float t[16];
    #pragma unroll
    for (int c = 0; c < 16; c++) t[c] = ts[c*72 + p];

    #pragma unroll 1
    for (int jj = 0; jj < 49; jj++) {
        int j = jj*4 + q4;                          // warp-uniform
        const float4* wv = (const float4*)&wsj[j*16];
        float4 w0 = wv[0], w1 = wv[1], w2 = wv[2], w3 = wv[3];
        float acc = bss[j];
        acc += w0.x*t[0]  + w0.y*t[1]  + w0.z*t[2]  + w0.w*t[3];
        acc += w1.x*t[4]  + w1.y*t[5]  + w1.z*t[6]  + w1.w*t[7];
        acc += w2.x*t[8]  + w2.y*t[9]  + w2.z*t[10] + w2.w*t[11];
        acc += w3.x*t[12] + w3.y*t[13] + w3.z*t[14] + w3.w*t[15];
        if (valid) g_w[j*PLANE + addr] = acc;
    }
}

// ---------------------------------------------------------------------------
// agg: involution aggregation + relu.
// Tile 32x16 px, 8 channels (half a group) per block. 128 threads,
// 4 px x 8 ch per thread. x-halo in swizzled smem (16B = 4 channels),
// per-pixel kernels read directly from gmem as float4.
// grid (4, 8, 8): x-tiles, y-tiles, group*2+half.
// ---------------------------------------------------------------------------
#define AGG_ROWS 22
#define AGG_PCH  40                       // chunks per (row, c4): 38 used, pad->40
#define AGG_CHUNKS (AGG_ROWS*2*AGG_PCH)   // 1760 chunks = 28160 B

__global__ __launch_bounds__(128) void k_agg(const float* __restrict__ src,
                                             float* __restrict__ dst)
{
    __shared__ alignas(16) float xs[AGG_CHUNKS*4];

    int g    = blockIdx.z >> 1;
    int half = blockIdx.z & 1;
    int x0 = blockIdx.x * 32, y0 = blockIdx.y * 16;
    int tid = threadIdx.x;

    // loader: 8 channels x 22 rows x 38 positions, zero-padded halo
    for (int i = tid; i < 8*22*38; i += 128) {
        int c = i / 836; int rem = i - c*836;
        int r = rem / 38; int p = rem - r*38;
        int gy = y0 + r - 3, gx = x0 + p - 3;
        float v = 0.f;
        if ((unsigned)gy < 126u && (unsigned)gx < 126u)
            v = src[(g*16 + half*8 + c)*PLANE + gy*WP + gx];
        int chunk = (r*2 + (c >> 2))*AGG_PCH + p;
        int byte = chunk * 16;
        int sw = byte ^ ((byte >> 3) & 0x70);
        *(float*)((char*)xs + sw + (c & 3)*4) = v;
    }
    __syncthreads();

    int ty = tid >> 3;            // 0..15
    int xb = (tid & 7) * 4;       // 0,4,...,28
    int gy = y0 + ty;
    if (gy >= 126) return;
    int gx0 = x0 + xb;

    const float* wbase = g_w + (g*49)*PLANE + gy*WP + gx0;

    float acc[8][4];
    #pragma unroll
    for (int cc = 0; cc < 8; cc++)
        #pragma unroll
        for (int q = 0; q < 4; q++) acc[cc][q] = 0.f;

    #pragma unroll 1
    for (int kh = 0; kh < 7; kh++) {
        float4 wv[7];
        #pragma unroll
        for (int kw = 0; kw < 7; kw++)
            wv[kw] = *(const float4*)(wbase + (kh*7 + kw)*PLANE);

        #pragma unroll
        for (int cg = 0; cg < 2; cg++) {
            int rowbase = ((ty + kh)*2 + cg)*AGG_PCH;
            float4 xq[10];
            #pragma unroll
            for (int j = 0; j < 10; j++) {
                int byte = (rowbase + xb + j) * 16;
                int sw = byte ^ ((byte >> 3) & 0x70);
                xq[j] = *(const float4*)((const char*)xs + sw);
            }
            #pragma unroll
            for (int kw = 0; kw < 7; kw++) {
                #pragma unroll
                for (int q = 0; q < 4; q++) {
                    float w = (q == 0) ? wv[kw].x : (q == 1) ? wv[kw].y
                            : (q == 2) ? wv[kw].z : wv[kw].w;
                    float4 xv = xq[q + kw];
                    acc[cg*4+0][q] += w * xv.x;
                    acc[cg*4+1][q] += w * xv.y;
                    acc[cg*4+2][q] += w * xv.z;
                    acc[cg*4+3][q] += w * xv.w;
                }
            }
        }
    }

    #pragma unroll
    for (int cc = 0; cc < 8; cc++) {
        int ch = g*16 + half*8 + cc;
        float* o = dst + ch*PLANE + gy*WP + gx0;
        #pragma unroll
        for (int q = 0; q < 4; q++)
            if (gx0 + q < 126) o[q] = fmaxf(acc[cc][q], 0.f);
    }
}

// ---------------------------------------------------------------------------
// conv_out: (64,126,126) -> (128,124,124), 3x3 valid conv.
// grid (124 rows, 4 oc-groups), block 256 = 8 colgroups x 32 oc.
// ---------------------------------------------------------------------------
#define CO_XS (16*3*132)
#define CO_WS (32*16*12)
#define CO_SMEM ((CO_XS + CO_WS) * 4)

__global__ __launch_bounds__(256) void k_conv_out(const float* __restrict__ src,
    const float* __restrict__ wt, const float* __restrict__ bias,
    float* __restrict__ out)
{
    extern __shared__ float sm[];
    float* xs  = sm;            // [16][3][132]
    float* wsh = sm + CO_XS;    // [32][16][12]
    int y = blockIdx.x;         // output row 0..123
    int ocg = blockIdx.y;       // 0..3
    int tid = threadIdx.x;
    int cg = tid & 7, oc_l = tid >> 3;
    int oc = ocg*32 + oc_l;
    float acc[16] = {};

    for (int icc = 0; icc < 4; icc++) {
        __syncthreads();
        for (int idx = tid; idx < CO_XS; idx += 256) {
            int ic = idx / 396; int rem = idx - ic*396;
            int r = rem / 132;  int col = rem - r*132;
            float v = 0.f;
            if (col < 126) v = src[(icc*16 + ic)*PLANE + (y + r)*WP + col];
            xs[idx] = v;
        }
        for (int idx = tid; idx < CO_WS; idx += 256) {
            int o = idx / 192; int rem = idx - o*192;
            int ic = rem / 12; int k = rem - ic*12;
            wsh[idx] = (k < 9) ? wt[(ocg*32 + o)*576 + (icc*16 + ic)*9 + k] : 0.f;
        }
        __syncthreads();

        #pragma unroll 2
        for (int ic = 0; ic < 16; ic++) {
            float wreg[9];
            {
                const float* wb = &wsh[(oc_l*16 + ic)*12];
                float4 w0 = *(const float4*)wb;
                float4 w1 = *(const float4*)(wb + 4);
                wreg[0]=w0.x; wreg[1]=w0.y; wreg[2]=w0.z; wreg[3]=w0.w;
                wreg[4]=w1.x; wreg[5]=w1.y; wreg[6]=w1.z; wreg[7]=w1.w;
                wreg[8]=wb[8];
            }
            #pragma unroll
            for (int kh = 0; kh < 3; kh++) {
                float xr[18];
                const float* xb = &xs[(ic*3 + kh)*132 + cg*16];
                float4 a0 = *(const float4*)(xb);
                float4 a1 = *(const float4*)(xb + 4);
                float4 a2 = *(const float4*)(xb + 8);
                float4 a3 = *(const float4*)(xb + 12);
                float2 a4 = *(const float2*)(xb + 16);
                xr[0]=a0.x; xr[1]=a0.y; xr[2]=a0.z; xr[3]=a0.w;
                xr[4]=a1.x; xr[5]=a1.y; xr[6]=a1.z; xr[7]=a1.w;
                xr[8]=a2.x; xr[9]=a2.y; xr[10]=a2.z; xr[11]=a2.w;
                xr[12]=a3.x; xr[13]=a3.y; xr[14]=a3.z; xr[15]=a3.w;
                xr[16]=a4.x; xr[17]=a4.y;
                #pragma unroll
                for (int kw = 0; kw < 3; kw++) {
                    float w = wreg[kh*3 + kw];
                    #pragma unroll
                    for (int p = 0; p < 16; p++)
                        acc[p] += w * xr[p + kw];
                }
            }
        }
    }

    float bv = bias[oc];
    int xbase = cg * 16;
    float* o = &out[(oc*124 + y)*124 + xbase];
    #pragma unroll
    for (int p = 0; p < 16; p++)
        if (xbase + p < 124) o[p] = acc[p] + bv;
}

// ---------------------------------------------------------------------------
extern "C" void kernel_launch(void* const* d_in, const int* in_sizes, int n_in,
                              void* d_out, int out_size)
{
    const float* input = (const float*)d_in[0];
    const float* ciw   = (const float*)d_in[1];
    const float* cib   = (const float*)d_in[2];
    const float* wr    = (const float*)d_in[3];
    const float* brr   = (const float*)d_in[4];
    const float* gmm   = (const float*)d_in[5];
    const float* bet   = (const float*)d_in[6];
    const float* mu    = (const float*)d_in[7];
    const float* var   = (const float*)d_in[8];
    const float* ws    = (const float*)d_in[9];
    const float* bs    = (const float*)d_in[10];
    const float* cow   = (const float*)d_in[11];
    const float* cob   = (const float*)d_in[12];

    float *px, *py;
    cudaGetSymbolAddress((void**)&px, g_x);
    cudaGetSymbolAddress((void**)&py, g_y);
    cudaFuncSetAttribute(k_conv_out, cudaFuncAttributeMaxDynamicSharedMemorySize, CO_SMEM);

    k_conv_in<<<dim3(63, 64), 256>>>(input, ciw, cib, px);

    float* cur = px;
    float* nxt = py;
    for (int l = 0; l < NLAYER; l++) {
        k_kgen<<<249, 256>>>(cur, wr + l*1024, brr + l*16, gmm + l*16, bet + l*16,
                             mu + l*16, var + l*16, ws + l*3136, bs + l*196);
        k_agg<<<dim3(4, 8, 8), 128>>>(cur, nxt);
        float* t = cur; cur = nxt; nxt = t;
    }
    k_conv_out<<<dim3(124, 4), 256, CO_SMEM>>>(cur, cow, cob, (float*)d_out);
}

// round 4
// speedup vs baseline: 1.9597x; 1.5350x over previous
#include <cuda_runtime.h>

#define Hh 126
#define Ww 126
#define WP 128
#define NPIX (Hh*Ww)        // 15876
#define PLANE (Hh*WP)       // 16128
#define NLAYER 6

#define SWZ(b) ((b) ^ (((b) >> 3) & 0x70))

// ping-pong activation buffers + involution weight buffer
__device__ float g_x[64*PLANE];     // ~4.1 MB
__device__ float g_y[64*PLANE];     // ~4.1 MB
__device__ float g_w[196*PLANE];    // ~12.6 MB

// dummy launch so ncu -s 5 lands on k_agg
__global__ void k_dummy() {}

// ---------------------------------------------------------------------------
// conv_in: (1,3,128,128) -> (1,64,126,126), 3x3 valid conv
// ---------------------------------------------------------------------------
__global__ __launch_bounds__(256) void k_conv_in(const float* __restrict__ in,
                                                 const float* __restrict__ wt,
                                                 const float* __restrict__ bias,
                                                 float* __restrict__ out)
{
    int t = blockIdx.x * 256 + threadIdx.x;      // over 126*128 padded plane
    int c = blockIdx.y;
    int y = t >> 7, x = t & 127;
    if (y >= Hh || x >= Ww) return;
    float acc = bias[c];
    const float* wc = wt + c * 27;
    #pragma unroll
    for (int i = 0; i < 3; i++)
        #pragma unroll
        for (int r = 0; r < 3; r++)
            #pragma unroll
            for (int s = 0; s < 3; s++)
                acc += wc[(i*3+r)*3+s] * in[(i*128 + (y+r))*128 + (x+s)];
    out[c*PLANE + y*WP + x] = acc;
}

// ---------------------------------------------------------------------------
// kgen v4: 256 threads / 16 pixels, 16 threads per pixel.
// Phase A: thread (p, c) computes one t value (64-wide dot via float4).
// Phase B: thread (p, c) computes j = c, c+16, ... (12-13 outputs).
// grid 993 -> ~53 warps/SM.
// ---------------------------------------------------------------------------
__global__ __launch_bounds__(256) void k_kgen(const float* __restrict__ src,
    const float* __restrict__ wr, const float* __restrict__ br,
    const float* __restrict__ gmm, const float* __restrict__ bet,
    const float* __restrict__ mu, const float* __restrict__ var,
    const float* __restrict__ ws, const float* __restrict__ bs)
{
    __shared__ alignas(16) float xs2[16*68];     // [p][ic] pad 68
    __shared__ alignas(16) float wrs2[16*68];    // [c][ic] pad 68
    __shared__ alignas(16) float wsj[196*16];    // [j][c] native layout
    __shared__ alignas(16) float bss[196];
    __shared__ alignas(16) float ts[16*20];      // [p][c] pad 20
    __shared__ float scs[16], shs[16];

    int tid = threadIdx.x;
    int pix0 = blockIdx.x * 16;
    int p = tid & 15;
    int c = tid >> 4;

    for (int i = tid; i < 1024; i += 256) wrs2[(i >> 6)*68 + (i & 63)] = wr[i];
    for (int i = tid; i < 3136; i += 256) wsj[i] = ws[i];
    if (tid < 196) bss[tid] = bs[tid];
    if (tid < 16) {
        float s = gmm[tid] * rsqrtf(var[tid] + 1e-5f);
        scs[tid] = s;
        shs[tid] = (br[tid] - mu[tid]) * s + bet[tid];
    }
    for (int i = tid; i < 1024; i += 256) {
        int ic = i >> 4, pp = i & 15;
        int px2 = pix0 + pp;
        float v = 0.f;
        if (px2 < NPIX) {
            int y2 = px2 / 126;
            v = src[ic*PLANE + y2*WP + (px2 - y2*126)];
        }
        xs2[pp*68 + ic] = v;
    }
    __syncthreads();

    // Phase A
    {
        float a = 0.f;
        #pragma unroll
        for (int i4 = 0; i4 < 16; i4++) {
            float4 xv = *(const float4*)&xs2[p*68 + i4*4];
            float4 wv = *(const float4*)&wrs2[c*68 + i4*4];
            a += xv.x*wv.x + xv.y*wv.y + xv.z*wv.z + xv.w*wv.w;
        }
        ts[p*20 + c] = fmaxf(a * scs[c] + shs[c], 0.f);
    }
    __syncthreads();

    // Phase B
    float t[16];
    #pragma unroll
    for (int k = 0; k < 4; k++) {
        float4 v = *(const float4*)&ts[p*20 + k*4];
        t[k*4] = v.x; t[k*4+1] = v.y; t[k*4+2] = v.z; t[k*4+3] = v.w;
    }
    int pix = pix0 + p;
    bool valid = pix < NPIX;
    int addr = 0;
    if (valid) { int yy = pix / 126; addr = yy*WP + (pix - yy*126); }

    #pragma unroll 1
    for (int j = c; j < 196; j += 16) {
        const float4* wv = (const float4*)&wsj[j*16];
        float4 w0 = wv[0], w1 = wv[1], w2 = wv[2], w3 = wv[3];
        float acc = bss[j];
        acc += w0.x*t[0]  + w0.y*t[1]  + w0.z*t[2]  + w0.w*t[3];
        acc += w1.x*t[4]  + w1.y*t[5]  + w1.z*t[6]  + w1.w*t[7];
        acc += w2.x*t[8]  + w2.y*t[9]  + w2.z*t[10] + w2.w*t[11];
        acc += w3.x*t[12] + w3.y*t[13] + w3.z*t[14] + w3.w*t[15];
        if (valid) g_w[j*PLANE + addr] = acc;
    }
}

// ---------------------------------------------------------------------------
// agg: involution aggregation + relu. 256 threads, 32x16 tile, 8 ch/block,
// 2 px x 8 ch per thread. grid (4, 8, 8).
// ---------------------------------------------------------------------------
#define AGG_ROWS 22
#define AGG_PCH  40
#define AGG_CHUNKS (AGG_ROWS*2*AGG_PCH)

__global__ __launch_bounds__(256) void k_agg(const float* __restrict__ src,
                                             float* __restrict__ dst)
{
    __shared__ alignas(16) float xs[AGG_CHUNKS*4];

    int g    = blockIdx.z >> 1;
    int half = blockIdx.z & 1;
    int x0 = blockIdx.x * 32, y0 = blockIdx.y * 16;
    int tid = threadIdx.x;

    for (int i = tid; i < 8*22*38; i += 256) {
        int c = i / 836; int rem = i - c*836;
        int r = rem / 38; int pp = rem - r*38;
        int gy = y0 + r - 3, gx = x0 + pp - 3;
        float v = 0.f;
        if ((unsigned)gy < 126u && (unsigned)gx < 126u)
            v = src[(g*16 + half*8 + c)*PLANE + gy*WP + gx];
        int chunk = (r*2 + (c >> 2))*AGG_PCH + pp;
        int byte = chunk * 16;
        *(float*)((char*)xs + SWZ(byte) + (c & 3)*4) = v;
    }
    __syncthreads();

    int ty = tid >> 4;            // 0..15
    int xp = (tid & 15) * 2;      // 0,2,...,30
    int gy = y0 + ty;
    if (gy >= 126) return;
    int gx0 = x0 + xp;

    const float* wbase = g_w + (g*49)*PLANE + gy*WP + gx0;

    float acc[8][2];
    #pragma unroll
    for (int cc = 0; cc < 8; cc++) { acc[cc][0] = 0.f; acc[cc][1] = 0.f; }

    #pragma unroll 1
    for (int kh = 0; kh < 7; kh++) {
        float2 wv[7];
        #pragma unroll
        for (int kw = 0; kw < 7; kw++)
            wv[kw] = *(const float2*)(wbase + (kh*7 + kw)*PLANE);

        #pragma unroll
        for (int cg = 0; cg < 2; cg++) {
            int rowbase = ((ty + kh)*2 + cg)*AGG_PCH;
            float4 xq[8];
            #pragma unroll
            for (int j = 0; j < 8; j++) {
                int byte = (rowbase + xp + j) * 16;
                xq[j] = *(const float4*)((const char*)xs + SWZ(byte));
            }
            #pragma unroll
            for (int kw = 0; kw < 7; kw++) {
                #pragma unroll
                for (int q = 0; q < 2; q++) {
                    float w = q ? wv[kw].y : wv[kw].x;
                    float4 xv = xq[q + kw];
                    acc[cg*4+0][q] += w * xv.x;
                    acc[cg*4+1][q] += w * xv.y;
                    acc[cg*4+2][q] += w * xv.z;
                    acc[cg*4+3][q] += w * xv.w;
                }
            }
        }
    }

    #pragma unroll
    for (int cc = 0; cc < 8; cc++) {
        int ch = g*16 + half*8 + cc;
        float* o = dst + ch*PLANE + gy*WP + gx0;
        #pragma unroll
        for (int q = 0; q < 2; q++)
            if (gx0 + q < 126) o[q] = fmaxf(acc[cc][q], 0.f);
    }
}

// ---------------------------------------------------------------------------
// conv_out v2: (64,126,126) -> (128,124,124). grid (124 rows, 2 oc-groups),
// block 256 = 8 colgroups x 32 oc-lanes, 2 oc x 16 px per thread.
// xs swizzled (XOR-128) to kill 128B-stride bank conflicts.
// ---------------------------------------------------------------------------
#define CO_XS (16*3*132)        // 6336 floats (25344 B = 198*128)
#define CO_WS (64*16*12)        // 12288 floats
#define CO_SMEM ((CO_XS + CO_WS) * 4)

__global__ __launch_bounds__(256) void k_conv_out(const float* __restrict__ src,
    const float* __restrict__ wt, const float* __restrict__ bias,
    float* __restrict__ out)
{
    extern __shared__ float sm[];
    float* xs  = sm;            // [16][3][132] swizzled
    float* wsh = sm + CO_XS;    // [64][16][12]
    int y = blockIdx.x;         // output row 0..123
    int ocg = blockIdx.y;       // 0..1
    int tid = threadIdx.x;
    int cg = tid & 7, ol = tid >> 3;      // ol 0..31
    float accA[16] = {}, accB[16] = {};

    for (int icc = 0; icc < 4; icc++) {
        __syncthreads();
        for (int idx = tid; idx < CO_XS; idx += 256) {
            int ic = idx / 396; int rem = idx - ic*396;
            int r = rem / 132;  int col = rem - r*132;
            float v = 0.f;
            if (col < 126) v = src[(icc*16 + ic)*PLANE + (y + r)*WP + col];
            *(float*)((char*)xs + SWZ(idx*4)) = v;
        }
        for (int idx = tid; idx < CO_WS; idx += 256) {
            int o = idx / 192; int rem = idx - o*192;
            int ic = rem / 12; int k = rem - ic*12;
            wsh[idx] = (k < 9) ? wt[(ocg*64 + o)*576 + (icc*16 + ic)*9 + k] : 0.f;
        }
        __syncthreads();

        #pragma unroll 1
        for (int ic = 0; ic < 16; ic++) {
            float wA[9], wB[9];
            {
                const float* wb = &wsh[(ol*16 + ic)*12];
                float4 w0 = *(const float4*)wb;
                float4 w1 = *(const float4*)(wb + 4);
                wA[0]=w0.x; wA[1]=w0.y; wA[2]=w0.z; wA[3]=w0.w;
                wA[4]=w1.x; wA[5]=w1.y; wA[6]=w1.z; wA[7]=w1.w;
                wA[8]=wb[8];
                const float* wc = &wsh[((ol+32)*16 + ic)*12];
                float4 v0 = *(const float4*)wc;
                float4 v1 = *(const float4*)(wc + 4);
                wB[0]=v0.x; wB[1]=v0.y; wB[2]=v0.z; wB[3]=v0.w;
                wB[4]=v1.x; wB[5]=v1.y; wB[6]=v1.z; wB[7]=v1.w;
                wB[8]=wc[8];
            }
            #pragma unroll
            for (int kh = 0; kh < 3; kh++) {
                float xr[18];
                int base = ((ic*3 + kh)*132 + cg*16) * 4;   // byte offset
                float4 a0 = *(const float4*)((const char*)xs + SWZ(base));
                float4 a1 = *(const float4*)((const char*)xs + SWZ(base + 16));
                float4 a2 = *(const float4*)((const char*)xs + SWZ(base + 32));
                float4 a3 = *(const float4*)((const char*)xs + SWZ(base + 48));
                float2 a4 = *(const float2*)((const char*)xs + SWZ(base + 64));
                xr[0]=a0.x; xr[1]=a0.y; xr[2]=a0.z; xr[3]=a0.w;
                xr[4]=a1.x; xr[5]=a1.y; xr[6]=a1.z; xr[7]=a1.w;
                xr[8]=a2.x; xr[9]=a2.y; xr[10]=a2.z; xr[11]=a2.w;
                xr[12]=a3.x; xr[13]=a3.y; xr[14]=a3.z; xr[15]=a3.w;
                xr[16]=a4.x; xr[17]=a4.y;
                #pragma unroll
                for (int kw = 0; kw < 3; kw++) {
                    float fa = wA[kh*3 + kw];
                    float fb = wB[kh*3 + kw];
                    #pragma unroll
                    for (int p = 0; p < 16; p++) {
                        accA[p] += fa * xr[p + kw];
                        accB[p] += fb * xr[p + kw];
                    }
                }
            }
        }
    }

    int ocA = ocg*64 + ol, ocB = ocA + 32;
    float bA = bias[ocA], bB = bias[ocB];
    int xbase = cg * 16;
    float* oA = &out[(ocA*124 + y)*124 + xbase];
    float* oB = &out[(ocB*124 + y)*124 + xbase];
    #pragma unroll
    for (int p = 0; p < 16; p++)
        if (xbase + p < 124) { oA[p] = accA[p] + bA; oB[p] = accB[p] + bB; }
}

// ---------------------------------------------------------------------------
extern "C" void kernel_launch(void* const* d_in, const int* in_sizes, int n_in,
                              void* d_out, int out_size)
{
    const float* input = (const float*)d_in[0];
    const float* ciw   = (const float*)d_in[1];
    const float* cib   = (const float*)d_in[2];
    const float* wr    = (const float*)d_in[3];
    const float* brr   = (const float*)d_in[4];
    const float* gmm   = (const float*)d_in[5];
    const float* bet   = (const float*)d_in[6];
    const float* mu    = (const float*)d_in[7];
    const float* var   = (const float*)d_in[8];
    const float* ws    = (const float*)d_in[9];
    const float* bs    = (const float*)d_in[10];
    const float* cow   = (const float*)d_in[11];
    const float* cob   = (const float*)d_in[12];

    float *px, *py;
    cudaGetSymbolAddress((void**)&px, g_x);
    cudaGetSymbolAddress((void**)&py, g_y);
    cudaFuncSetAttribute(k_conv_out, cudaFuncAttributeMaxDynamicSharedMemorySize, CO_SMEM);

    k_dummy<<<1, 32>>>();
    k_conv_in<<<dim3(63, 64), 256>>>(input, ciw, cib, px);

    float* cur = px;
    float* nxt = py;
    for (int l = 0; l < NLAYER; l++) {
        k_kgen<<<993, 256>>>(cur, wr + l*1024, brr + l*16, gmm + l*16, bet + l*16,
                             mu + l*16, var + l*16, ws + l*3136, bs + l*196);
        k_agg<<<dim3(4, 8, 8), 256>>>(cur, nxt);
        float* t = cur; cur = nxt; nxt = t;
    }
    k_conv_out<<<dim3(124, 2), 256, CO_SMEM>>>(cur, cow, cob, (float*)d_out);
}